// round 1
// baseline (speedup 1.0000x reference)
#include <cuda_runtime.h>
#include <cfloat>

#define BB 4
#define CC 64
#define NN 65536
#define KK 16
#define TILE_N 64

// 67 MB transposed-features scratch: [B][N][C]
__device__ float g_ft[(size_t)BB * NN * CC];

// ---------------------------------------------------------------------------
// Kernel 1: transpose features [B][C][N] -> g_ft [B][N][C]
// Standard 32x32 smem tile, 32x8 threads, 4 rows per thread.
// ---------------------------------------------------------------------------
__global__ void transpose_kernel(const float* __restrict__ f) {
    __shared__ float tile[32][33];
    int b  = blockIdx.z;
    int c0 = blockIdx.y * 32;
    int n0 = blockIdx.x * 32;

    const float* src = f + ((size_t)b * CC + c0) * NN + n0;
#pragma unroll
    for (int j = 0; j < 4; j++) {
        int c = threadIdx.y + 8 * j;
        tile[c][threadIdx.x] = src[(size_t)c * NN + threadIdx.x];
    }
    __syncthreads();

    float* dst = g_ft + ((size_t)b * NN + n0) * CC + c0;
#pragma unroll
    for (int j = 0; j < 4; j++) {
        int nl = threadIdx.y + 8 * j;
        dst[(size_t)nl * CC + threadIdx.x] = tile[threadIdx.x][nl];
    }
}

// ---------------------------------------------------------------------------
// Kernel 2: gather + max.
// Block = 256 threads (8 warps), handles one batch b and TILE_N=64 columns.
// Phase 1: stage the 16xTILE_N index tile (coalesced along n).
// Phase 2: half-warp per column; 16 lanes x float4 = 64 channels.
//          Each of the K=16 gathers is a contiguous 256B read of g_ft[b][idx][:].
//          Results go to smem tile s_out[C][TILE_N+1].
// Phase 3: write out[b][c][n0..n0+63] with lanes spanning n (coalesced 256B rows).
// ---------------------------------------------------------------------------
__global__ __launch_bounds__(256) void gather_max_kernel(
    const int* __restrict__ nb, float* __restrict__ out)
{
    __shared__ int   s_idx[KK][TILE_N];
    __shared__ float s_out[CC][TILE_N + 1];

    int b  = blockIdx.y;
    int n0 = blockIdx.x * TILE_N;
    int tid = threadIdx.x;

    // Phase 1: load index tile (K rows of 64 consecutive ints, coalesced)
    const int* nbp = nb + (size_t)b * KK * NN + n0;
    for (int i = tid; i < KK * TILE_N; i += 256) {
        int k = i >> 6;            // i / TILE_N
        int j = i & (TILE_N - 1);  // i % TILE_N
        s_idx[k][j] = nbp[(size_t)k * NN + j];
    }
    __syncthreads();

    // Phase 2: gather-max
    int warp = tid >> 5;
    int lane = tid & 31;
    int half = lane >> 4;   // which column of the pair this half-warp owns
    int cg   = lane & 15;   // channel group: channels [4*cg, 4*cg+3]

    const float4* ftb = (const float4*)(g_ft + (size_t)b * NN * CC);

#pragma unroll
    for (int p = 0; p < 4; p++) {
        int col = warp * 8 + p * 2 + half;  // 8 warps x 8 cols = 64 columns
        float4 acc = make_float4(-FLT_MAX, -FLT_MAX, -FLT_MAX, -FLT_MAX);
#pragma unroll
        for (int k = 0; k < KK; k++) {
            int idx = s_idx[k][col];                       // smem broadcast
            float4 v = __ldg(&ftb[(size_t)idx * (CC / 4) + cg]);
            acc.x = fmaxf(acc.x, v.x);
            acc.y = fmaxf(acc.y, v.y);
            acc.z = fmaxf(acc.z, v.z);
            acc.w = fmaxf(acc.w, v.w);
        }
        int c = cg * 4;
        s_out[c + 0][col] = acc.x;
        s_out[c + 1][col] = acc.y;
        s_out[c + 2][col] = acc.z;
        s_out[c + 3][col] = acc.w;
    }
    __syncthreads();

    // Phase 3: coalesced output write (channel-major layout [B][C][N])
    float* outp = out + (size_t)b * CC * NN + n0;
    for (int i = tid; i < CC * TILE_N; i += 256) {
        int c = i >> 6;   // i / 64
        int j = i & 63;   // i % 64
        outp[(size_t)c * NN + j] = s_out[c][j];
    }
}

extern "C" void kernel_launch(void* const* d_in, const int* in_sizes, int n_in,
                              void* d_out, int out_size)
{
    const float* features     = (const float*)d_in[0];
    const int*   neighborhood = (const int*)d_in[1];
    float*       out          = (float*)d_out;

    dim3 tgrid(NN / 32, CC / 32, BB);  // (2048, 2, 4)
    dim3 tblk(32, 8);
    transpose_kernel<<<tgrid, tblk>>>(features);

    dim3 ggrid(NN / TILE_N, BB);       // (1024, 4)
    gather_max_kernel<<<ggrid, 256>>>(neighborhood, out);
}

// round 2
// speedup vs baseline: 1.0174x; 1.0174x over previous
#include <cuda_runtime.h>
#include <cfloat>

#define BB 4
#define CC 64
#define NN 65536
#define KK 16
#define TILE_N 64

// 67 MB transposed-features scratch: [B][N][C]
__device__ float g_ft[(size_t)BB * NN * CC];

// ---------------------------------------------------------------------------
// Kernel 1: transpose features [B][C][N] -> g_ft [B][N][C]
// 64x64 float tile, 256 threads, float4 on both global sides.
// smem tile padded to 68 floats/row: float4 stores conflict-free, and the
// column-gather reads (stride 68) are conflict-free scalars.
// ---------------------------------------------------------------------------
__global__ __launch_bounds__(256) void transpose_kernel(const float* __restrict__ f) {
    __shared__ float tile[64][68];
    int b  = blockIdx.z;
    int c0 = blockIdx.y * 64;
    int n0 = blockIdx.x * 64;

    int tid = threadIdx.x;
    int tx  = tid & 15;   // float4 column within tile (n/4)
    int ty  = tid >> 4;   // 0..15

    // Load: 64 rows (c) x 16 float4 (n). Each thread does 4 rows.
    const float4* src = (const float4*)(f + ((size_t)b * CC + c0) * NN + n0);
#pragma unroll
    for (int j = 0; j < 4; j++) {
        int c = ty + 16 * j;
        float4 v = __ldcs(&src[(size_t)c * (NN / 4) + tx]);
        *(float4*)&tile[c][tx * 4] = v;
    }
    __syncthreads();

    // Store: 64 rows (n) x 16 float4 (c). Gather columns from smem.
    float* dst = g_ft + ((size_t)b * NN + n0) * CC + c0;
#pragma unroll
    for (int j = 0; j < 4; j++) {
        int n = ty + 16 * j;
        int c = tx * 4;
        float4 v;
        v.x = tile[c + 0][n];
        v.y = tile[c + 1][n];
        v.z = tile[c + 2][n];
        v.w = tile[c + 3][n];
        *(float4*)&dst[(size_t)n * CC + c] = v;
    }
}

// ---------------------------------------------------------------------------
// Kernel 2: gather + max.
// Block = 256 threads (8 warps), one batch b, TILE_N=64 columns.
// Half-warp per column: 16 lanes x float4 = 64 channels, each gather is a
// contiguous 256B read. Two column-pairs processed concurrently per warp
// (independent accumulator sets) to double loads-in-flight.
// ---------------------------------------------------------------------------
__global__ __launch_bounds__(256) void gather_max_kernel(
    const int* __restrict__ nb, float* __restrict__ out)
{
    __shared__ int   s_idx[KK][TILE_N];
    __shared__ float s_out[CC][TILE_N + 1];

    int b  = blockIdx.y;
    int n0 = blockIdx.x * TILE_N;
    int tid = threadIdx.x;

    // Phase 1: load index tile (K rows of 64 consecutive ints, coalesced)
    const int* nbp = nb + (size_t)b * KK * NN + n0;
    for (int i = tid; i < KK * TILE_N; i += 256) {
        int k = i >> 6;
        int j = i & (TILE_N - 1);
        s_idx[k][j] = nbp[(size_t)k * NN + j];
    }
    __syncthreads();

    // Phase 2: gather-max, two independent column streams per warp
    int warp = tid >> 5;
    int lane = tid & 31;
    int half = lane >> 4;
    int cg   = lane & 15;

    const float4* ftb = (const float4*)(g_ft + (size_t)b * NN * CC);

#pragma unroll
    for (int p = 0; p < 2; p++) {
        int colA = warp * 8 + p * 2 + half;      // cols 0..3 of warp's 8
        int colB = colA + 4;                      // cols 4..7
        float4 accA = make_float4(-FLT_MAX, -FLT_MAX, -FLT_MAX, -FLT_MAX);
        float4 accB = accA;
#pragma unroll
        for (int k = 0; k < KK; k++) {
            int idxA = s_idx[k][colA];
            int idxB = s_idx[k][colB];
            float4 vA = __ldg(&ftb[(size_t)idxA * (CC / 4) + cg]);
            float4 vB = __ldg(&ftb[(size_t)idxB * (CC / 4) + cg]);
            accA.x = fmaxf(accA.x, vA.x);
            accA.y = fmaxf(accA.y, vA.y);
            accA.z = fmaxf(accA.z, vA.z);
            accA.w = fmaxf(accA.w, vA.w);
            accB.x = fmaxf(accB.x, vB.x);
            accB.y = fmaxf(accB.y, vB.y);
            accB.z = fmaxf(accB.z, vB.z);
            accB.w = fmaxf(accB.w, vB.w);
        }
        int c = cg * 4;
        s_out[c + 0][colA] = accA.x;
        s_out[c + 1][colA] = accA.y;
        s_out[c + 2][colA] = accA.z;
        s_out[c + 3][colA] = accA.w;
        s_out[c + 0][colB] = accB.x;
        s_out[c + 1][colB] = accB.y;
        s_out[c + 2][colB] = accB.z;
        s_out[c + 3][colB] = accB.w;
    }
    __syncthreads();

    // Phase 3: coalesced output write, streaming hint (don't pollute L2)
    float* outp = out + (size_t)b * CC * NN + n0;
    for (int i = tid; i < CC * TILE_N; i += 256) {
        int c = i >> 6;
        int j = i & 63;
        __stcs(&outp[(size_t)c * NN + j], s_out[c][j]);
    }
}

extern "C" void kernel_launch(void* const* d_in, const int* in_sizes, int n_in,
                              void* d_out, int out_size)
{
    const float* features     = (const float*)d_in[0];
    const int*   neighborhood = (const int*)d_in[1];
    float*       out          = (float*)d_out;

    dim3 tgrid(NN / 64, CC / 64, BB);  // (1024, 1, 4)
    transpose_kernel<<<tgrid, 256>>>(features);

    dim3 ggrid(NN / TILE_N, BB);       // (1024, 4)
    gather_max_kernel<<<ggrid, 256>>>(neighborhood, out);
}